// round 11
// baseline (speedup 1.0000x reference)
#include <cuda_runtime.h>
#include <cuda_bf16.h>

// IDW interpolation, POWER=2:  w = 1/d^2 (sqrt cancels).
//
// Round 11: 4-STATION GROUPING. R7-R10 showed the kernel is issue-bound
// (issue slots ~1.8-2.5x ideal op count from register-pair marshaling;
// scheduling knobs all flat). Grouping 4 stations under one reciprocal:
//   t12=a1*a2  t34=a3*a4  prod=t12*t34
//   sum_w  num = s12*t34 + s34*t12   (s12=a1+a2, s34=a3+a4)
//   sum_wv num = n12*t34 + n34*t12   (n12=v1*a2+v2*a1, n34=v3*a4+v4*a3)
//   w-contrib  = num * rcp(prod)
// -> 31 wide ops + ONE f2_rcp (2 MUFU + 4 mov) per 4 stations per pack,
// vs pairing's 28 wide + TWO f2_rcp. ~10% fewer issue slots, MUFU halved,
// rcp mov-bloat amortized 2x. Underflow-safe: prod >= ~1e-21 for this
// data (eps=1e-12 seed; min pairwise d2 ~ 2e-9).
//
// d==0: fold +1e-12 into d^2 (dominating weight -> same ratio; no branch).
// Shape: 2 point-pack chains/thread, 8 split-warps, 2048 blocks (R8/R10).

#define NSTATIONS 512
#define SPLITS 8
#define GROUPS_PER_SPLIT 16            // 64 stations per split-warp
#define PACKS_PER_BLOCK 64             // 128 grid points per block
#define TPB 256                        // 8 warps: split = warp id
#define NPACKS 131072                  // total points / 2

typedef unsigned long long u64;

__device__ __forceinline__ u64 f2_pack(float lo, float hi) {
    u64 r; asm("mov.b64 %0, {%1, %2};" : "=l"(r) : "f"(lo), "f"(hi)); return r;
}
__device__ __forceinline__ void f2_unpack(u64 a, float& lo, float& hi) {
    asm("mov.b64 {%0, %1}, %2;" : "=f"(lo), "=f"(hi) : "l"(a));
}
__device__ __forceinline__ u64 f2_add(u64 a, u64 b) {
    u64 r; asm("add.rn.f32x2 %0, %1, %2;" : "=l"(r) : "l"(a), "l"(b)); return r;
}
__device__ __forceinline__ u64 f2_mul(u64 a, u64 b) {
    u64 r; asm("mul.rn.f32x2 %0, %1, %2;" : "=l"(r) : "l"(a), "l"(b)); return r;
}
__device__ __forceinline__ u64 f2_fma(u64 a, u64 b, u64 c) {
    u64 r; asm("fma.rn.f32x2 %0, %1, %2, %3;" : "=l"(r) : "l"(a), "l"(b), "l"(c)); return r;
}
__device__ __forceinline__ float frcp(float a) {
    float r; asm("rcp.approx.f32 %0, %1;" : "=f"(r) : "f"(a)); return r;
}
__device__ __forceinline__ u64 f2_rcp(u64 a) {
    float lo, hi; f2_unpack(a, lo, hi);
    return f2_pack(frcp(lo), frcp(hi));
}

struct GroupState { u64 swn, wvn, prod; };

// One 4-station group body for one point-pack chain (no rcp).
__device__ __forceinline__ GroupState group_body(
    u64 gx, u64 gy,
    ulonglong2 c1, ulonglong2 c2, ulonglong2 c3, ulonglong2 c4,
    ulonglong2 v12, ulonglong2 v34, u64 eps2)
{
    // distances (a_i seeded with eps)
    u64 dx1 = f2_add(gx, c1.x), dy1 = f2_add(gy, c1.y);
    u64 a1  = f2_fma(dy1, dy1, eps2);  a1 = f2_fma(dx1, dx1, a1);
    u64 dx2 = f2_add(gx, c2.x), dy2 = f2_add(gy, c2.y);
    u64 a2  = f2_fma(dy2, dy2, eps2);  a2 = f2_fma(dx2, dx2, a2);
    u64 dx3 = f2_add(gx, c3.x), dy3 = f2_add(gy, c3.y);
    u64 a3  = f2_fma(dy3, dy3, eps2);  a3 = f2_fma(dx3, dx3, a3);
    u64 dx4 = f2_add(gx, c4.x), dy4 = f2_add(gy, c4.y);
    u64 a4  = f2_fma(dy4, dy4, eps2);  a4 = f2_fma(dx4, dx4, a4);

    // pair combine
    u64 t12 = f2_mul(a1, a2);
    u64 t34 = f2_mul(a3, a4);
    u64 s12 = f2_add(a1, a2);
    u64 s34 = f2_add(a3, a4);
    u64 n12 = f2_fma(v12.y, a1, f2_mul(v12.x, a2));  // v1*a2 + v2*a1
    u64 n34 = f2_fma(v34.y, a3, f2_mul(v34.x, a4));  // v3*a4 + v4*a3

    GroupState g;
    g.prod = f2_mul(t12, t34);
    g.swn  = f2_fma(s34, t12, f2_mul(s12, t34));     // sum-of-weights numerator
    g.wvn  = f2_fma(n34, t12, f2_mul(n12, t34));     // weighted-value numerator
    return g;
}

__global__ __launch_bounds__(TPB) void idw_fused(
    const float* __restrict__ station_coords,  // (B, S, 2)
    const float* __restrict__ station_values,  // (B, S)
    const float* __restrict__ grid_points,     // (B, P, 2)
    float* __restrict__ out,                   // (B, P) flat
    int P)
{
    // 128 groups of 4 stations, 6 ulonglong2 (16B) each -> LDS.128 broadcast:
    //  [0]=(nx1,ny1) [1]=(nx2,ny2) [2]=(nx3,ny3) [3]=(nx4,ny4)
    //  [4]=(vv1,vv2) [5]=(vv3,vv4)     (nx = (-x,-x) etc, vv = (v,v))
    __shared__ ulonglong2 sh2[(NSTATIONS / 4) * 6];   // 12 KB
    __shared__ float4 red[SPLITS * PACKS_PER_BLOCK];  // 8 KB partials

    const int tid   = threadIdx.x;
    const int split = tid >> 5;                    // warp id, 0..7
    const int lane  = tid & 31;
    const int packbase = blockIdx.x * PACKS_PER_BLOCK;
    const int b = (packbase * 2) / P;  // 128 points/block divides P: one batch

    // Stage: one station PAIR per thread (pair p = stations 2p,2p+1).
    // Group g = p>>1, half h = p&1. 1 LDG.128 + 1 LDG.64 -> 3 STS.128.
    {
        const int g = tid >> 1, h = tid & 1;
        const float4 c = reinterpret_cast<const float4*>(
            station_coords + (size_t)b * NSTATIONS * 2)[tid];
        const float2 v = reinterpret_cast<const float2*>(
            station_values + (size_t)b * NSTATIONS)[tid];
        ulonglong2* dst = &sh2[g * 6];
        dst[h * 2 + 0] = make_ulonglong2(f2_pack(-c.x, -c.x), f2_pack(-c.y, -c.y));
        dst[h * 2 + 1] = make_ulonglong2(f2_pack(-c.z, -c.z), f2_pack(-c.w, -c.w));
        dst[4 + h]     = make_ulonglong2(f2_pack(v.x, v.x),   f2_pack(v.y, v.y));
    }
    __syncthreads();

    // Two packs per thread (chains 0/1), coalesced float4 loads.
    const float4 a0 = reinterpret_cast<const float4*>(grid_points)[packbase + lane];
    const float4 a1 = reinterpret_cast<const float4*>(grid_points)[packbase + 32 + lane];
    const u64 gx0 = f2_pack(a0.x, a0.z), gy0 = f2_pack(a0.y, a0.w);
    const u64 gx1 = f2_pack(a1.x, a1.z), gy1 = f2_pack(a1.y, a1.w);

    const u64 eps2 = f2_pack(1e-12f, 1e-12f);
    u64 ws0 = 0ull, vs0 = 0ull, ws1 = 0ull, vs1 = 0ull;

    const ulonglong2* base2 = sh2 + (size_t)split * GROUPS_PER_SPLIT * 6;

    // Software pipeline: rcp of group g-1 issues before body of group g.
    GroupState s0, s1;
    {
        const ulonglong2 c1 = base2[0], c2 = base2[1], c3 = base2[2],
                         c4 = base2[3], v12 = base2[4], v34 = base2[5];
        s0 = group_body(gx0, gy0, c1, c2, c3, c4, v12, v34, eps2);
        s1 = group_body(gx1, gy1, c1, c2, c3, c4, v12, v34, eps2);
    }

    #pragma unroll 4
    for (int g = 1; g < GROUPS_PER_SPLIT; g++) {
        u64 r0 = f2_rcp(s0.prod);        // MUFU latency hidden by body below
        u64 r1 = f2_rcp(s1.prod);

        const ulonglong2* gb = base2 + g * 6;
        const ulonglong2 c1 = gb[0], c2 = gb[1], c3 = gb[2],
                         c4 = gb[3], v12 = gb[4], v34 = gb[5];
        GroupState t0 = group_body(gx0, gy0, c1, c2, c3, c4, v12, v34, eps2);
        GroupState t1 = group_body(gx1, gy1, c1, c2, c3, c4, v12, v34, eps2);

        ws0 = f2_fma(s0.swn, r0, ws0);
        vs0 = f2_fma(s0.wvn, r0, vs0);
        ws1 = f2_fma(s1.swn, r1, ws1);
        vs1 = f2_fma(s1.wvn, r1, vs1);

        s0 = t0;
        s1 = t1;
    }
    {   // epilogue
        u64 r0 = f2_rcp(s0.prod);
        u64 r1 = f2_rcp(s1.prod);
        ws0 = f2_fma(s0.swn, r0, ws0);
        vs0 = f2_fma(s0.wvn, r0, vs0);
        ws1 = f2_fma(s1.swn, r1, ws1);
        vs1 = f2_fma(s1.wvn, r1, vs1);
    }

    // Partials -> smem
    {
        float w0, w1, n0, n1;
        f2_unpack(ws0, w0, w1);  f2_unpack(vs0, n0, n1);
        red[split * PACKS_PER_BLOCK + lane] = make_float4(w0, w1, n0, n1);
        f2_unpack(ws1, w0, w1);  f2_unpack(vs1, n0, n1);
        red[split * PACKS_PER_BLOCK + 32 + lane] = make_float4(w0, w1, n0, n1);
    }
    __syncthreads();

    // Threads 0..63 reduce 8 splits for one pack each (fixed order, det.)
    if (tid < PACKS_PER_BLOCK) {
        float4 acc = red[tid];
        #pragma unroll
        for (int k = 1; k < SPLITS; k++) {
            float4 t = red[k * PACKS_PER_BLOCK + tid];  // conflict-free LDS.128
            acc.x += t.x; acc.y += t.y; acc.z += t.z; acc.w += t.w;
        }
        float2 r;
        r.x = acc.z * frcp(acc.x);
        r.y = acc.w * frcp(acc.y);
        reinterpret_cast<float2*>(out)[packbase + tid] = r;
    }
}

extern "C" void kernel_launch(void* const* d_in, const int* in_sizes, int n_in,
                              void* d_out, int out_size) {
    const float* station_coords = (const float*)d_in[0];  // (B,S,2)
    const float* station_values = (const float*)d_in[1];  // (B,S)
    const float* grid_points    = (const float*)d_in[2];  // (B,P,2)
    float* out = (float*)d_out;

    const int S = NSTATIONS;                 // 512 per problem spec
    const int B = in_sizes[1] / S;           // 2
    const int P = in_sizes[2] / (B * 2);     // 131072

    const int blocks = NPACKS / PACKS_PER_BLOCK;  // 2048 blocks, 16384 warps
    idw_fused<<<blocks, TPB>>>(station_coords, station_values, grid_points,
                               out, P);
}

// round 12
// speedup vs baseline: 1.5554x; 1.5554x over previous
#include <cuda_runtime.h>
#include <cuda_bf16.h>

// IDW interpolation, POWER=2:  w = 1/d^2 (sqrt cancels).
//
// Round 12: revert to R8 pairing shape (grouping R11 regressed: RF-bank
// conflicts doubled fma busy). Issue model now closed: wide f32x2 ops
// dual-pump (2 issue slots each) -> kernel is issue-bound at ~64k
// slots/SMSP, 67% efficiency. This round attacks efficiency only:
//   1. FULL unroll of the 32-pair loop (no loop slots; big scheduling
//      window so ptxas batches LDS.128 early).
//   2. Manual interleave of the two independent point-pack chains.
//   3. rcp software-pipelined one iteration ahead (R10).
//
// Pairing identity for d2 values a,b (1 rcp per 2 stations per point):
//   w1+w2       = (a+b)/(a*b)
//   w1*v1+w2*v2 = (v1*b + v2*a)/(a*b)
// d==0: fold +1e-12 into d^2 (dominating weight -> same ratio; no branch;
// pair product can't underflow).

#define NSTATIONS 512
#define SPLITS 8
#define PAIRS_PER_SPLIT 32             // 64 stations per split-warp
#define PACKS_PER_BLOCK 64             // 128 grid points per block
#define TPB 256                        // 8 warps: split = warp id
#define NPACKS 131072                  // total points / 2

typedef unsigned long long u64;

__device__ __forceinline__ u64 f2_pack(float lo, float hi) {
    u64 r; asm("mov.b64 %0, {%1, %2};" : "=l"(r) : "f"(lo), "f"(hi)); return r;
}
__device__ __forceinline__ void f2_unpack(u64 a, float& lo, float& hi) {
    asm("mov.b64 {%0, %1}, %2;" : "=f"(lo), "=f"(hi) : "l"(a));
}
__device__ __forceinline__ u64 f2_add(u64 a, u64 b) {
    u64 r; asm("add.rn.f32x2 %0, %1, %2;" : "=l"(r) : "l"(a), "l"(b)); return r;
}
__device__ __forceinline__ u64 f2_mul(u64 a, u64 b) {
    u64 r; asm("mul.rn.f32x2 %0, %1, %2;" : "=l"(r) : "l"(a), "l"(b)); return r;
}
__device__ __forceinline__ u64 f2_fma(u64 a, u64 b, u64 c) {
    u64 r; asm("fma.rn.f32x2 %0, %1, %2, %3;" : "=l"(r) : "l"(a), "l"(b), "l"(c)); return r;
}
__device__ __forceinline__ float frcp(float a) {
    float r; asm("rcp.approx.f32 %0, %1;" : "=f"(r) : "f"(a)); return r;
}
__device__ __forceinline__ u64 f2_rcp(u64 a) {
    float lo, hi; f2_unpack(a, lo, hi);
    return f2_pack(frcp(lo), frcp(hi));
}

__global__ __launch_bounds__(TPB) void idw_fused(
    const float* __restrict__ station_coords,  // (B, S, 2)
    const float* __restrict__ station_values,  // (B, S)
    const float* __restrict__ grid_points,     // (B, P, 2)
    float* __restrict__ out,                   // (B, P) flat
    int P)
{
    // 256 station pairs, 6 u64 each (3 x 16B -> LDS.128 broadcast):
    //  [0]=(-x1,-x1) [1]=(-y1,-y1) [2]=(-x2,-x2) [3]=(-y2,-y2) [4]=(v1,v1) [5]=(v2,v2)
    __shared__ u64 sh[(NSTATIONS / 2) * 6];           // 12 KB
    __shared__ float4 red[SPLITS * PACKS_PER_BLOCK];  // 8 KB partials

    const int tid   = threadIdx.x;
    const int split = tid >> 5;                    // warp id, 0..7
    const int lane  = tid & 31;
    const int packbase = blockIdx.x * PACKS_PER_BLOCK;
    const int b = (packbase * 2) / P;  // 128 points/block divides P: one batch

    // Stage: one station pair per thread (LDG.128 + LDG.64 -> 3x STS.128)
    {
        const float4 c = reinterpret_cast<const float4*>(
            station_coords + (size_t)b * NSTATIONS * 2)[tid];
        const float2 v = reinterpret_cast<const float2*>(
            station_values + (size_t)b * NSTATIONS)[tid];
        ulonglong2* dst = reinterpret_cast<ulonglong2*>(sh + tid * 6);
        dst[0] = make_ulonglong2(f2_pack(-c.x, -c.x), f2_pack(-c.y, -c.y));
        dst[1] = make_ulonglong2(f2_pack(-c.z, -c.z), f2_pack(-c.w, -c.w));
        dst[2] = make_ulonglong2(f2_pack(v.x, v.x),   f2_pack(v.y, v.y));
    }
    __syncthreads();

    // Two packs per thread (chains 0/1), coalesced float4 loads.
    const float4 a0 = reinterpret_cast<const float4*>(grid_points)[packbase + lane];
    const float4 a1 = reinterpret_cast<const float4*>(grid_points)[packbase + 32 + lane];
    const u64 gx0 = f2_pack(a0.x, a0.z), gy0 = f2_pack(a0.y, a0.w);
    const u64 gx1 = f2_pack(a1.x, a1.z), gy1 = f2_pack(a1.y, a1.w);

    const u64 eps2 = f2_pack(1e-12f, 1e-12f);
    u64 ws0 = 0ull, vs0 = 0ull, ws1 = 0ull, vs1 = 0ull;

    const ulonglong2* sh2 = reinterpret_cast<const ulonglong2*>(sh)
                          + (size_t)split * PAIRS_PER_SPLIT * 3;

    // Pipeline state: previous pair's (sum, num, prod) per chain.
    u64 psum0, pnum0, pprod0, psum1, pnum1, pprod1;

    // Prologue: pair 0, chains interleaved.
    {
        const ulonglong2 c1 = sh2[0], c2 = sh2[1], vv = sh2[2];
        u64 dxA0 = f2_add(gx0, c1.x);      u64 dxB0 = f2_add(gx1, c1.x);
        u64 dyA0 = f2_add(gy0, c1.y);      u64 dyB0 = f2_add(gy1, c1.y);
        u64 daA  = f2_fma(dyA0, dyA0, eps2); u64 daB = f2_fma(dyB0, dyB0, eps2);
        daA      = f2_fma(dxA0, dxA0, daA);  daB     = f2_fma(dxB0, dxB0, daB);
        u64 dxA1 = f2_add(gx0, c2.x);      u64 dxB1 = f2_add(gx1, c2.x);
        u64 dyA1 = f2_add(gy0, c2.y);      u64 dyB1 = f2_add(gy1, c2.y);
        u64 dbA  = f2_fma(dyA1, dyA1, eps2); u64 dbB = f2_fma(dyB1, dyB1, eps2);
        dbA      = f2_fma(dxA1, dxA1, dbA);  dbB     = f2_fma(dxB1, dxB1, dbB);
        psum0  = f2_add(daA, dbA);         psum1  = f2_add(daB, dbB);
        pprod0 = f2_mul(daA, dbA);         pprod1 = f2_mul(daB, dbB);
        pnum0  = f2_mul(vv.x, dbA);        pnum1  = f2_mul(vv.x, dbB);
        pnum0  = f2_fma(vv.y, daA, pnum0); pnum1  = f2_fma(vv.y, daB, pnum1);
    }

    #pragma unroll
    for (int p = 1; p < PAIRS_PER_SPLIT; p++) {
        // Previous pair's reciprocals issue first: MUFU hidden under body.
        u64 r0 = f2_rcp(pprod0);
        u64 r1 = f2_rcp(pprod1);

        const ulonglong2 c1 = sh2[p * 3 + 0];  // LDS.128 broadcast
        const ulonglong2 c2 = sh2[p * 3 + 1];
        const ulonglong2 vv = sh2[p * 3 + 2];

        // Current pair body, chains interleaved op-by-op.
        u64 dxA0 = f2_add(gx0, c1.x);      u64 dxB0 = f2_add(gx1, c1.x);
        u64 dyA0 = f2_add(gy0, c1.y);      u64 dyB0 = f2_add(gy1, c1.y);
        u64 daA  = f2_fma(dyA0, dyA0, eps2); u64 daB = f2_fma(dyB0, dyB0, eps2);
        daA      = f2_fma(dxA0, dxA0, daA);  daB     = f2_fma(dxB0, dxB0, daB);
        u64 dxA1 = f2_add(gx0, c2.x);      u64 dxB1 = f2_add(gx1, c2.x);
        u64 dyA1 = f2_add(gy0, c2.y);      u64 dyB1 = f2_add(gy1, c2.y);
        u64 dbA  = f2_fma(dyA1, dyA1, eps2); u64 dbB = f2_fma(dyB1, dyB1, eps2);
        dbA      = f2_fma(dxA1, dxA1, dbA);  dbB     = f2_fma(dxB1, dxB1, dbB);

        // Accumulate previous pair (r ready by now).
        ws0 = f2_fma(psum0, r0, ws0);      ws1 = f2_fma(psum1, r1, ws1);
        vs0 = f2_fma(pnum0, r0, vs0);      vs1 = f2_fma(pnum1, r1, vs1);

        // Current pair combine -> becomes "previous" for next iteration.
        psum0  = f2_add(daA, dbA);         psum1  = f2_add(daB, dbB);
        pprod0 = f2_mul(daA, dbA);         pprod1 = f2_mul(daB, dbB);
        pnum0  = f2_mul(vv.x, dbA);        pnum1  = f2_mul(vv.x, dbB);
        pnum0  = f2_fma(vv.y, daA, pnum0); pnum1  = f2_fma(vv.y, daB, pnum1);
    }
    {   // Epilogue: last pair.
        u64 r0 = f2_rcp(pprod0);
        u64 r1 = f2_rcp(pprod1);
        ws0 = f2_fma(psum0, r0, ws0);      ws1 = f2_fma(psum1, r1, ws1);
        vs0 = f2_fma(pnum0, r0, vs0);      vs1 = f2_fma(pnum1, r1, vs1);
    }

    // Partials -> smem
    {
        float w0, w1, n0, n1;
        f2_unpack(ws0, w0, w1);  f2_unpack(vs0, n0, n1);
        red[split * PACKS_PER_BLOCK + lane] = make_float4(w0, w1, n0, n1);
        f2_unpack(ws1, w0, w1);  f2_unpack(vs1, n0, n1);
        red[split * PACKS_PER_BLOCK + 32 + lane] = make_float4(w0, w1, n0, n1);
    }
    __syncthreads();

    // Threads 0..63 reduce 8 splits for one pack each (fixed order, det.)
    if (tid < PACKS_PER_BLOCK) {
        float4 acc = red[tid];
        #pragma unroll
        for (int k = 1; k < SPLITS; k++) {
            float4 t = red[k * PACKS_PER_BLOCK + tid];  // conflict-free LDS.128
            acc.x += t.x; acc.y += t.y; acc.z += t.z; acc.w += t.w;
        }
        float2 r;
        r.x = acc.z * frcp(acc.x);
        r.y = acc.w * frcp(acc.y);
        reinterpret_cast<float2*>(out)[packbase + tid] = r;
    }
}

extern "C" void kernel_launch(void* const* d_in, const int* in_sizes, int n_in,
                              void* d_out, int out_size) {
    const float* station_coords = (const float*)d_in[0];  // (B,S,2)
    const float* station_values = (const float*)d_in[1];  // (B,S)
    const float* grid_points    = (const float*)d_in[2];  // (B,P,2)
    float* out = (float*)d_out;

    const int S = NSTATIONS;                 // 512 per problem spec
    const int B = in_sizes[1] / S;           // 2
    const int P = in_sizes[2] / (B * 2);     // 131072

    const int blocks = NPACKS / PACKS_PER_BLOCK;  // 2048 blocks, 16384 warps
    idw_fused<<<blocks, TPB>>>(station_coords, station_values, grid_points,
                               out, P);
}

// round 14
// speedup vs baseline: 1.6882x; 1.0853x over previous
#include <cuda_runtime.h>
#include <cuda_bf16.h>

// IDW interpolation, POWER=2:  w = 1/d^2 (sqrt cancels).
//
// Round 13: combine the two best-measured variants. Core-time ranking:
// R9 (ILP-4) 45.5us < R8 (ILP-2) 46.1 < R10 (ILP-2 + pipelined rcp) 46.7.
// This round = R9 shape + R10's rcp software pipeline (never tested
// together): 4 independent point-pack chains per thread, and each loop
// iteration issues the PREVIOUS iteration's 8 MUFU.RCP first, computes the
// 4 current bodies (56 independent wide ops fill the MUFU+MOV shadow),
// then accumulates the previous groups. Moderate unroll, no manual
// interleave (R12 showed hand-scheduling bloats alu-pipe MOV marshaling).
//
// Pairing identity for d2 values a,b (1 rcp per 2 stations per point):
//   w1+w2       = (a+b)/(a*b)
//   w1*v1+w2*v2 = (v1*b + v2*a)/(a*b)
// d==0: fold +1e-12 into d^2 (dominating weight -> same ratio; no branch;
// pair product can't underflow). 14 FP + 1 rcp per 2st-pt is the proven
// op floor (difference-of-squares variants cancel catastrophically).

#define NSTATIONS 512
#define SPLITS 8
#define PAIRS_PER_SPLIT 32             // 64 stations per split-warp
#define CHAINS 4                       // point-packs per thread (8 points)
#define PACKS_PER_BLOCK 128            // 32 lanes * 4 chains
#define TPB 256                        // 8 warps: split = warp id
#define NPACKS 131072                  // total points / 2

typedef unsigned long long u64;

__device__ __forceinline__ u64 f2_pack(float lo, float hi) {
    u64 r; asm("mov.b64 %0, {%1, %2};" : "=l"(r) : "f"(lo), "f"(hi)); return r;
}
__device__ __forceinline__ void f2_unpack(u64 a, float& lo, float& hi) {
    asm("mov.b64 {%0, %1}, %2;" : "=f"(lo), "=f"(hi) : "l"(a));
}
__device__ __forceinline__ u64 f2_add(u64 a, u64 b) {
    u64 r; asm("add.rn.f32x2 %0, %1, %2;" : "=l"(r) : "l"(a), "l"(b)); return r;
}
__device__ __forceinline__ u64 f2_mul(u64 a, u64 b) {
    u64 r; asm("mul.rn.f32x2 %0, %1, %2;" : "=l"(r) : "l"(a), "l"(b)); return r;
}
__device__ __forceinline__ u64 f2_fma(u64 a, u64 b, u64 c) {
    u64 r; asm("fma.rn.f32x2 %0, %1, %2, %3;" : "=l"(r) : "l"(a), "l"(b), "l"(c)); return r;
}
__device__ __forceinline__ float frcp(float a) {
    float r; asm("rcp.approx.f32 %0, %1;" : "=f"(r) : "f"(a)); return r;
}
__device__ __forceinline__ u64 f2_rcp(u64 a) {
    float lo, hi; f2_unpack(a, lo, hi);
    return f2_pack(frcp(lo), frcp(hi));
}

struct PairState { u64 sum, num, prod; };

// One pair-body for one point-pack chain (no rcp).
__device__ __forceinline__ PairState pair_body(
    u64 gx, u64 gy, ulonglong2 c1, ulonglong2 c2, ulonglong2 vv, u64 eps2)
{
    u64 dx1 = f2_add(gx, c1.x);
    u64 dy1 = f2_add(gy, c1.y);
    u64 da  = f2_fma(dy1, dy1, eps2);
    da      = f2_fma(dx1, dx1, da);        // a = d2 of station 1
    u64 dx2 = f2_add(gx, c2.x);
    u64 dy2 = f2_add(gy, c2.y);
    u64 db  = f2_fma(dy2, dy2, eps2);
    db      = f2_fma(dx2, dx2, db);        // b = d2 of station 2
    PairState s;
    s.sum  = f2_add(da, db);               // a + b
    s.prod = f2_mul(da, db);               // a * b
    s.num  = f2_mul(vv.x, db);
    s.num  = f2_fma(vv.y, da, s.num);      // v1*b + v2*a
    return s;
}

__global__ __launch_bounds__(TPB) void idw_fused(
    const float* __restrict__ station_coords,  // (B, S, 2)
    const float* __restrict__ station_values,  // (B, S)
    const float* __restrict__ grid_points,     // (B, P, 2)
    float* __restrict__ out,                   // (B, P) flat
    int P)
{
    // 256 station pairs, 6 u64 each (3 x 16B -> LDS.128 broadcast):
    //  [0]=(-x1,-x1) [1]=(-y1,-y1) [2]=(-x2,-x2) [3]=(-y2,-y2) [4]=(v1,v1) [5]=(v2,v2)
    __shared__ u64 sh[(NSTATIONS / 2) * 6];           // 12 KB
    __shared__ float4 red[SPLITS * PACKS_PER_BLOCK];  // 16 KB partials

    const int tid   = threadIdx.x;
    const int split = tid >> 5;                    // warp id, 0..7
    const int lane  = tid & 31;
    const int packbase = blockIdx.x * PACKS_PER_BLOCK;
    const int b = (packbase * 2) / P;  // 256 points/block divides P: one batch

    // Stage: one station pair per thread (LDG.128 + LDG.64 -> 3x STS.128)
    {
        const float4 c = reinterpret_cast<const float4*>(
            station_coords + (size_t)b * NSTATIONS * 2)[tid];
        const float2 v = reinterpret_cast<const float2*>(
            station_values + (size_t)b * NSTATIONS)[tid];
        ulonglong2* dst = reinterpret_cast<ulonglong2*>(sh + tid * 6);
        dst[0] = make_ulonglong2(f2_pack(-c.x, -c.x), f2_pack(-c.y, -c.y));
        dst[1] = make_ulonglong2(f2_pack(-c.z, -c.z), f2_pack(-c.w, -c.w));
        dst[2] = make_ulonglong2(f2_pack(v.x, v.x),   f2_pack(v.y, v.y));
    }
    __syncthreads();

    // 4 packs per thread: chain q owns pack (lane + 32*q). Coalesced float4.
    u64 gx[CHAINS], gy[CHAINS], ws[CHAINS], vs[CHAINS];
    #pragma unroll
    for (int q = 0; q < CHAINS; q++) {
        const float4 a = reinterpret_cast<const float4*>(
            grid_points)[packbase + 32 * q + lane];
        gx[q] = f2_pack(a.x, a.z);
        gy[q] = f2_pack(a.y, a.w);
        ws[q] = 0ull;
        vs[q] = 0ull;
    }

    const u64 eps2 = f2_pack(1e-12f, 1e-12f);
    const ulonglong2* sh2 = reinterpret_cast<const ulonglong2*>(sh)
                          + (size_t)split * PAIRS_PER_SPLIT * 3;

    // Software pipeline: rcp of pair p-1 issues before the body of pair p.
    PairState st[CHAINS];
    {
        const ulonglong2 c1 = sh2[0], c2 = sh2[1], vv = sh2[2];
        #pragma unroll
        for (int q = 0; q < CHAINS; q++)
            st[q] = pair_body(gx[q], gy[q], c1, c2, vv, eps2);
    }

    #pragma unroll 2
    for (int p = 1; p < PAIRS_PER_SPLIT; p++) {
        // Previous pair's reciprocals first: 8 MUFU hidden under the bodies.
        u64 r[CHAINS];
        #pragma unroll
        for (int q = 0; q < CHAINS; q++)
            r[q] = f2_rcp(st[q].prod);

        const ulonglong2 c1 = sh2[p * 3 + 0];  // LDS.128 broadcast
        const ulonglong2 c2 = sh2[p * 3 + 1];
        const ulonglong2 vv = sh2[p * 3 + 2];

        PairState nx[CHAINS];
        #pragma unroll
        for (int q = 0; q < CHAINS; q++)
            nx[q] = pair_body(gx[q], gy[q], c1, c2, vv, eps2);

        #pragma unroll
        for (int q = 0; q < CHAINS; q++) {
            ws[q] = f2_fma(st[q].sum, r[q], ws[q]);
            vs[q] = f2_fma(st[q].num, r[q], vs[q]);
            st[q] = nx[q];
        }
    }
    {   // Epilogue: last pair.
        #pragma unroll
        for (int q = 0; q < CHAINS; q++) {
            u64 r = f2_rcp(st[q].prod);
            ws[q] = f2_fma(st[q].sum, r, ws[q]);
            vs[q] = f2_fma(st[q].num, r, vs[q]);
        }
    }

    // Partials -> smem
    #pragma unroll
    for (int q = 0; q < CHAINS; q++) {
        float w0, w1, n0, n1;
        f2_unpack(ws[q], w0, w1);
        f2_unpack(vs[q], n0, n1);
        red[split * PACKS_PER_BLOCK + 32 * q + lane] = make_float4(w0, w1, n0, n1);
    }
    __syncthreads();

    // Threads 0..127 reduce 8 splits for one pack each (fixed order, det.)
    if (tid < PACKS_PER_BLOCK) {
        float4 acc = red[tid];
        #pragma unroll
        for (int k = 1; k < SPLITS; k++) {
            float4 t = red[k * PACKS_PER_BLOCK + tid];  // conflict-free LDS.128
            acc.x += t.x; acc.y += t.y; acc.z += t.z; acc.w += t.w;
        }
        float2 r;
        r.x = acc.z * frcp(acc.x);
        r.y = acc.w * frcp(acc.y);
        reinterpret_cast<float2*>(out)[packbase + tid] = r;
    }
}

extern "C" void kernel_launch(void* const* d_in, const int* in_sizes, int n_in,
                              void* d_out, int out_size) {
    const float* station_coords = (const float*)d_in[0];  // (B,S,2)
    const float* station_values = (const float*)d_in[1];  // (B,S)
    const float* grid_points    = (const float*)d_in[2];  // (B,P,2)
    float* out = (float*)d_out;

    const int S = NSTATIONS;                 // 512 per problem spec
    const int B = in_sizes[1] / S;           // 2
    const int P = in_sizes[2] / (B * 2);     // 131072

    const int blocks = NPACKS / PACKS_PER_BLOCK;  // 1024 blocks, 8192 warps
    idw_fused<<<blocks, TPB>>>(station_coords, station_values, grid_points,
                               out, P);
}